// round 7
// baseline (speedup 1.0000x reference)
#include <cuda_runtime.h>
#include <cstdint>

// -------------------- problem constants --------------------
#define B_SZ 4096
#define I_SZ 1024
#define H_SZ 2048
#define NSTEPS 5
#define DT_C 0.1f

// -------------------- GEMM tiling --------------------
#define BM 128
#define BN 128
#define BK 32            // two 16-float sub-tiles per stage
#define NSTAGE 3
#define THREADS 256

#define SUB_A   8192                    // 128 rows x 64B
#define SUB_B   8192
#define SUB_BYTES (3 * 8192)            // A + B0 + B1
#define STAGE_BYTES (2 * SUB_BYTES)     // two k-subs = 49152
#define SMEM_TOTAL (NSTAGE * STAGE_BYTES)  // 147456 (>= 128*132*4 epilogue tile)

// -------------------- scratch --------------------
__device__ float g_C1[B_SZ * H_SZ];
__device__ float g_C2[B_SZ * H_SZ];
__device__ float g_hA[B_SZ * H_SZ];
__device__ float g_hB[B_SZ * H_SZ];

// -------------------- PTX helpers --------------------
__device__ __forceinline__ void cp16(uint32_t smem, const void* g) {
    asm volatile("cp.async.cg.shared.global [%0], [%1], 16;" :: "r"(smem), "l"(g) : "memory");
}
__device__ __forceinline__ void cp_commit() {
    asm volatile("cp.async.commit_group;" ::: "memory");
}
template <int N>
__device__ __forceinline__ void cp_wait() {
    asm volatile("cp.async.wait_group %0;" :: "n"(N) : "memory");
}
__device__ __forceinline__ void ldsm4(uint32_t* r, uint32_t a) {
    asm volatile("ldmatrix.sync.aligned.m8n8.x4.shared.b16 {%0,%1,%2,%3}, [%4];"
                 : "=r"(r[0]), "=r"(r[1]), "=r"(r[2]), "=r"(r[3]) : "r"(a));
}
__device__ __forceinline__ void mma_tf32(float* d, const uint32_t* a, const uint32_t* b) {
    asm volatile(
        "mma.sync.aligned.m16n8k8.row.col.f32.tf32.tf32.f32 "
        "{%0,%1,%2,%3}, {%4,%5,%6,%7}, {%8,%9}, {%0,%1,%2,%3};"
        : "+f"(d[0]), "+f"(d[1]), "+f"(d[2]), "+f"(d[3])
        : "r"(a[0]), "r"(a[1]), "r"(a[2]), "r"(a[3]), "r"(b[0]), "r"(b[1]));
}

// swizzled smem byte address within an 8K sub-block (64B rows, 4x16B chunks)
__device__ __forceinline__ uint32_t swadr(uint32_t base, int r, int g) {
    const int c = g ^ (r & 3) ^ ((r >> 2) & 1);
    return base + (uint32_t)(r * 64 + c * 16);
}

// -------------------- fused dual-output tf32 GEMM --------------------
// Warps 0-3: acc = A @ B0^T (G1 / tau path), full 128x128 tile (64x64 per warp).
// Warps 4-7: acc = A @ B1^T (G2 / rec path), same tile coordinates.
// LIQ=0: group0 writes o0 = acc + e0[col]; group1 writes o1 = acc + e1[col].
// LIQ=1: group0 stages G1 in smem; group1 computes liquid update:
//        e0=C1, e1=C2, e2=h_in, e3=tau_base; o0=h_out, o1=tau_out (optional).
template <int LIQ>
__global__ void __launch_bounds__(THREADS, 1)
gemm2_tf32(const float* __restrict__ A, int lda,
           const float* __restrict__ B0, int ldb0,
           const float* __restrict__ B1, int ldb1,
           int K,
           float* __restrict__ o0, float* __restrict__ o1,
           const float* __restrict__ e0, const float* __restrict__ e1,
           const float* __restrict__ e2, const float* __restrict__ e3)
{
    extern __shared__ __align__(1024) char smem[];
    const uint32_t sb = (uint32_t)__cvta_generic_to_shared(smem);

    const int tid  = threadIdx.x;
    const int lane = tid & 31;
    const int wid  = tid >> 5;
    const int g01  = wid >> 2;          // 0: B0 output, 1: B1 output
    const int wq   = wid & 3;
    const int wm   = (wq >> 1) * 64;    // 0 / 64
    const int wn   = (wq & 1) * 64;     // 0 / 64

    const int m0 = blockIdx.y * BM;
    const int n0 = blockIdx.x * BN;

    // ---- loader coordinates: row lr (0..127), two 16B chunks ----
    const int lr  = tid >> 1;
    const int lg0 = (tid & 1) * 2;
    const int lg1 = lg0 + 1;
    const float* gA  = A  + (long)(m0 + lr) * lda;
    const float* gB0 = B0 + (long)(n0 + lr) * ldb0;
    const float* gB1 = B1 + (long)(n0 + lr) * ldb1;

    // ---- ldmatrix lane coordinates ----
    const int arow = (lane & 7) + ((lane >> 3) & 1) * 8;
    const int agof = (lane >> 4);
    const int brow = (lane & 7) + ((lane >> 4) & 1) * 8;
    const int bgof = (lane >> 3) & 1;

    float acc[4][8][4];
#pragma unroll
    for (int mt = 0; mt < 4; mt++)
#pragma unroll
        for (int nt = 0; nt < 8; nt++)
#pragma unroll
            for (int r = 0; r < 4; r++) acc[mt][nt][r] = 0.f;

    const int nK = K / BK;

    // ---- stage loader: 12 cp16/thread ----
    auto load_stage = [&](int s, int kt) {
        const uint32_t st = sb + s * STAGE_BYTES;
#pragma unroll
        for (int sub = 0; sub < 2; sub++) {
            const uint32_t sA   = st + sub * SUB_BYTES;
            const uint32_t sB0s = sA + SUB_A;
            const uint32_t sB1s = sB0s + SUB_B;
            const int koff = kt * BK + sub * 16;
            cp16(swadr(sA,   lr, lg0), gA  + koff + lg0 * 4);
            cp16(swadr(sA,   lr, lg1), gA  + koff + lg1 * 4);
            cp16(swadr(sB0s, lr, lg0), gB0 + koff + lg0 * 4);
            cp16(swadr(sB0s, lr, lg1), gB0 + koff + lg1 * 4);
            cp16(swadr(sB1s, lr, lg0), gB1 + koff + lg0 * 4);
            cp16(swadr(sB1s, lr, lg1), gB1 + koff + lg1 * 4);
        }
    };

    // prologue
#pragma unroll
    for (int s = 0; s < NSTAGE - 1; s++) {
        load_stage(s, s);
        cp_commit();
    }

    for (int kt = 0; kt < nK; kt++) {
        cp_wait<NSTAGE - 2>();
        __syncthreads();

        const int kload = kt + NSTAGE - 1;
        if (kload < nK) load_stage(kload % NSTAGE, kload);
        cp_commit();

        const uint32_t st = sb + (kt % NSTAGE) * STAGE_BYTES;

#pragma unroll
        for (int ks = 0; ks < 4; ks++) {
            const uint32_t sA  = st + (ks >> 1) * SUB_BYTES;
            const uint32_t sBg = sA + SUB_A + g01 * SUB_B;
            const int kq = ks & 1;

            uint32_t af[4][4], bf[4][4];
#pragma unroll
            for (int mt = 0; mt < 4; mt++)
                ldsm4(af[mt], swadr(sA, wm + mt * 16 + arow, 2 * kq + agof));
#pragma unroll
            for (int p = 0; p < 4; p++)
                ldsm4(bf[p], swadr(sBg, wn + p * 16 + brow, 2 * kq + bgof));
#pragma unroll
            for (int mt = 0; mt < 4; mt++)
#pragma unroll
                for (int p = 0; p < 4; p++) {
                    mma_tf32(acc[mt][2 * p],     af[mt], &bf[p][0]);
                    mma_tf32(acc[mt][2 * p + 1], af[mt], &bf[p][2]);
                }
        }
    }

    // ---- epilogue ----
    const int grp = lane >> 2;
    const int tig = lane & 3;

    if (LIQ == 0) {
        float* o          = g01 ? o1 : o0;
        const float* bias = g01 ? e1 : e0;
#pragma unroll
        for (int mt = 0; mt < 4; mt++) {
            const int row0 = m0 + wm + mt * 16 + grp;
#pragma unroll
            for (int nt = 0; nt < 8; nt++) {
                const int col = n0 + wn + nt * 8 + 2 * tig;
                const float b0 = __ldg(bias + col), b1 = __ldg(bias + col + 1);
                float2 u0, u1;
                u0.x = acc[mt][nt][0] + b0;  u0.y = acc[mt][nt][1] + b1;
                u1.x = acc[mt][nt][2] + b0;  u1.y = acc[mt][nt][3] + b1;
                *(float2*)(o + (long)row0 * H_SZ + col)       = u0;
                *(float2*)(o + (long)(row0 + 8) * H_SZ + col) = u1;
            }
        }
    } else {
        // exchange G1 (group0 acc) through smem, group1 computes liquid step
        float* g1s = (float*)smem;     // 128 x 132 padded tile
        __syncthreads();
        if (g01 == 0) {
#pragma unroll
            for (int mt = 0; mt < 4; mt++) {
                const int r0 = wm + mt * 16 + grp;
#pragma unroll
                for (int nt = 0; nt < 8; nt++) {
                    const int col = wn + nt * 8 + 2 * tig;
                    *(float2*)(g1s + r0 * 132 + col)       = make_float2(acc[mt][nt][0], acc[mt][nt][1]);
                    *(float2*)(g1s + (r0 + 8) * 132 + col) = make_float2(acc[mt][nt][2], acc[mt][nt][3]);
                }
            }
        }
        __syncthreads();
        if (g01 == 1) {
#pragma unroll
            for (int mt = 0; mt < 4; mt++) {
                const int lr0 = wm + mt * 16 + grp;
#pragma unroll
                for (int nt = 0; nt < 8; nt++) {
                    const int lcol = wn + nt * 8 + 2 * tig;
                    const int col  = n0 + lcol;
                    const float2 tb = *(const float2*)(e3 + col);
#pragma unroll
                    for (int rr = 0; rr < 2; rr++) {
                        const int lrow = lr0 + rr * 8;
                        const long off = (long)(m0 + lrow) * H_SZ + col;
                        const float2 g1v = *(const float2*)(g1s + lrow * 132 + lcol);
                        const float2 c1v = *(const float2*)(e0 + off);
                        const float2 c2v = *(const float2*)(e1 + off);
                        const float2 hv  = *(const float2*)(e2 + off);
                        float2 hn, tv;
                        {
                            const float g2  = acc[mt][nt][2 * rr];
                            const float tl  = c2v.x + g1v.x;
                            const float sg  = 1.f / (1.f + __expf(-tl));
                            const float tau = tb.x * (0.5f + sg);
                            const float act = tanhf(g2 + c1v.x);
                            hn.x = hv.x + DT_C * (act - hv.x) / tau;
                            tv.x = tau;
                        }
                        {
                            const float g2  = acc[mt][nt][2 * rr + 1];
                            const float tl  = c2v.y + g1v.y;
                            const float sg  = 1.f / (1.f + __expf(-tl));
                            const float tau = tb.y * (0.5f + sg);
                            const float act = tanhf(g2 + c1v.y);
                            hn.y = hv.y + DT_C * (act - hv.y) / tau;
                            tv.y = tau;
                        }
                        *(float2*)(o0 + off) = hn;
                        if (o1) *(float2*)(o1 + off) = tv;
                    }
                }
            }
        }
    }
}

// -------------------- launcher --------------------
extern "C" void kernel_launch(void* const* d_in, const int* in_sizes, int n_in,
                              void* d_out, int out_size)
{
    (void)in_sizes; (void)n_in; (void)out_size;

    const float* x           = (const float*)d_in[0];
    const float* hidden      = (const float*)d_in[1];
    const float* W_rec       = (const float*)d_in[2];
    const float* W_in_w      = (const float*)d_in[3];
    const float* W_in_b      = (const float*)d_in[4];
    const float* tau_base    = (const float*)d_in[5];
    const float* tau_adapt_w = (const float*)d_in[6];
    const float* tau_adapt_b = (const float*)d_in[7];

    float* out_h   = (float*)d_out;
    float* out_tau = out_h + (long)B_SZ * H_SZ;

    float *C1, *C2, *hA, *hB;
    cudaGetSymbolAddress((void**)&C1, g_C1);
    cudaGetSymbolAddress((void**)&C2, g_C2);
    cudaGetSymbolAddress((void**)&hA, g_hA);
    cudaGetSymbolAddress((void**)&hB, g_hB);

    cudaFuncSetAttribute(gemm2_tf32<0>, cudaFuncAttributeMaxDynamicSharedMemorySize, SMEM_TOTAL);
    cudaFuncSetAttribute(gemm2_tf32<1>, cudaFuncAttributeMaxDynamicSharedMemorySize, SMEM_TOTAL);

    const int ldtau = I_SZ + H_SZ;     // 3072
    dim3 gg(H_SZ / BN, B_SZ / BM);     // (16, 32) = 512 CTAs

    // invariants: C1 = x@W_in^T + W_in_b ; C2 = x@tau_x^T + tau_adapt_b
    gemm2_tf32<0><<<gg, THREADS, SMEM_TOTAL>>>(
        x, I_SZ,
        W_in_w, I_SZ,
        tau_adapt_w, ldtau,
        I_SZ,
        C1, C2, W_in_b, tau_adapt_b, nullptr, nullptr);

    // 5 fused steps: G1 = h@tau_h^T (warps 0-3), G2 = h@W_rec^T (warps 4-7)
    const float* h = hidden;
    float* bufs[2] = {hA, hB};
    for (int s = 0; s < NSTEPS; s++) {
        float* ho = (s == NSTEPS - 1) ? out_h   : bufs[s & 1];
        float* to = (s == NSTEPS - 1) ? out_tau : nullptr;
        gemm2_tf32<1><<<gg, THREADS, SMEM_TOTAL>>>(
            h, H_SZ,
            tau_adapt_w + I_SZ, ldtau,
            W_rec, H_SZ,
            H_SZ,
            ho, to, C1, C2, h, tau_base);
        h = ho;
    }
}

// round 8
// speedup vs baseline: 1.0088x; 1.0088x over previous
#include <cuda_runtime.h>
#include <cstdint>

// -------------------- problem constants --------------------
#define B_SZ 4096
#define I_SZ 1024
#define H_SZ 2048
#define NSTEPS 5
#define DT_C 0.1f

// -------------------- GEMM tiling (R4 inner loop, half-size CTA) ----------
#define BM 128
#define BN 128
#define BK 16
#define NSTAGE 4
#define THREADS 128

#define SA_BYTES (BM * BK * 4)                 // 8192
#define SB_BYTES (BN * BK * 4)                 // 8192
#define STAGE_BYTES (SA_BYTES + SB_BYTES)      // 16384
#define SMEM_TOTAL (NSTAGE * STAGE_BYTES)      // 65536

// -------------------- scratch --------------------
__device__ float g_C1[B_SZ * H_SZ];
__device__ float g_C2[B_SZ * H_SZ];
__device__ float g_G1[B_SZ * H_SZ];
__device__ float g_G2[B_SZ * H_SZ];
__device__ float g_h [B_SZ * H_SZ];

// -------------------- PTX helpers --------------------
__device__ __forceinline__ void cp16(uint32_t smem, const void* g) {
    asm volatile("cp.async.cg.shared.global [%0], [%1], 16;" :: "r"(smem), "l"(g) : "memory");
}
__device__ __forceinline__ void cp_commit() {
    asm volatile("cp.async.commit_group;" ::: "memory");
}
template <int N>
__device__ __forceinline__ void cp_wait() {
    asm volatile("cp.async.wait_group %0;" :: "n"(N) : "memory");
}
__device__ __forceinline__ void ldsm4(uint32_t* r, uint32_t a) {
    asm volatile("ldmatrix.sync.aligned.m8n8.x4.shared.b16 {%0,%1,%2,%3}, [%4];"
                 : "=r"(r[0]), "=r"(r[1]), "=r"(r[2]), "=r"(r[3]) : "r"(a));
}
__device__ __forceinline__ void mma_tf32(float* d, const uint32_t* a, const uint32_t* b) {
    asm volatile(
        "mma.sync.aligned.m16n8k8.row.col.f32.tf32.tf32.f32 "
        "{%0,%1,%2,%3}, {%4,%5,%6,%7}, {%8,%9}, {%0,%1,%2,%3};"
        : "+f"(d[0]), "+f"(d[1]), "+f"(d[2]), "+f"(d[3])
        : "r"(a[0]), "r"(a[1]), "r"(a[2]), "r"(a[3]), "r"(b[0]), "r"(b[1]));
}

// swizzled smem byte address for 16B chunk (row r of 64B, chunk g of 4)
__device__ __forceinline__ uint32_t swadr(uint32_t base, int r, int g) {
    const int c = g ^ (r & 3) ^ ((r >> 2) & 1);
    return base + (uint32_t)(r * 64 + c * 16);
}

// -------------------- dual-B tf32 GEMM, 128-thread CTA, 2 CTAs/SM ---------
// C_half[M, H_SZ]: tile = A[m0:+128, :K] @ Bh[n0:+128, :K]^T (+bias_h)
// grid (32, M/128): blockIdx.x = half*16 + nblk.
__global__ void __launch_bounds__(THREADS, 2)
gemm_dual_tf32(const float* __restrict__ A, int lda,
               const float* __restrict__ B0, int ldb0, float* __restrict__ C0,
               const float* __restrict__ bias0,
               const float* __restrict__ B1, int ldb1, float* __restrict__ C1,
               const float* __restrict__ bias1,
               int K)
{
    extern __shared__ __align__(1024) char smem[];
    const uint32_t sb = (uint32_t)__cvta_generic_to_shared(smem);

    const int tid  = threadIdx.x;
    const int lane = tid & 31;
    const int wid  = tid >> 5;           // 0..3
    const int wm   = (wid >> 1) * 64;    // 0 / 64
    const int wn   = (wid & 1) * 64;     // 0 / 64

    const int half = blockIdx.x >> 4;
    const int nblk = blockIdx.x & 15;
    const int m0 = blockIdx.y * BM;
    const int n0 = nblk * BN;

    const float* Bw   = half ? B1 : B0;
    const int    ldb  = half ? ldb1 : ldb0;
    float*       C    = half ? C1 : C0;
    const float* bias = half ? bias1 : bias0;

    // ---- loader coordinates: row lr (0..63, plus +64), chunks lc/lc+1 ----
    const int lr = tid >> 1;
    const int lc = (tid & 1) * 2;
    const float* gA = A  + (long)(m0 + lr) * lda + lc * 4;
    const float* gB = Bw + (long)(n0 + lr) * ldb + lc * 4;
    const long strideA64 = (long)64 * lda;
    const long strideB64 = (long)64 * ldb;

    // ---- ldmatrix lane coordinates (identical to R4) ----
    const int arow = (lane & 7) + ((lane >> 3) & 1) * 8;
    const int agof = (lane >> 4);
    const int brow = (lane & 7) + ((lane >> 4) & 1) * 8;
    const int bgof = (lane >> 3) & 1;

    float acc[4][8][4];
#pragma unroll
    for (int mt = 0; mt < 4; mt++)
#pragma unroll
        for (int nt = 0; nt < 8; nt++)
#pragma unroll
            for (int r = 0; r < 4; r++) acc[mt][nt][r] = 0.f;

    const int nK = K / BK;

    // ---- stage loader (8 cp.async per thread) ----
    auto load_stage = [&](int s, int kt) {
        const uint32_t sA = sb + s * STAGE_BYTES;
        const uint32_t sB = sA + SA_BYTES;
        const int koff = kt * BK;
        cp16(swadr(sA, lr,      lc),     gA + koff);
        cp16(swadr(sA, lr,      lc + 1), gA + koff + 4);
        cp16(swadr(sA, lr + 64, lc),     gA + koff + strideA64);
        cp16(swadr(sA, lr + 64, lc + 1), gA + koff + strideA64 + 4);
        cp16(swadr(sB, lr,      lc),     gB + koff);
        cp16(swadr(sB, lr,      lc + 1), gB + koff + 4);
        cp16(swadr(sB, lr + 64, lc),     gB + koff + strideB64);
        cp16(swadr(sB, lr + 64, lc + 1), gB + koff + strideB64 + 4);
    };

    // prologue: prefetch NSTAGE-1 stages
#pragma unroll
    for (int s = 0; s < NSTAGE - 1; s++) {
        load_stage(s, s);
        cp_commit();
    }

    for (int kt = 0; kt < nK; kt++) {
        cp_wait<NSTAGE - 2>();
        __syncthreads();

        const int kload = kt + NSTAGE - 1;
        if (kload < nK) load_stage(kload & (NSTAGE - 1), kload);
        cp_commit();

        const uint32_t sA = sb + (kt & (NSTAGE - 1)) * STAGE_BYTES;
        const uint32_t sB = sA + SA_BYTES;

#pragma unroll
        for (int ks = 0; ks < 2; ks++) {
            uint32_t af[4][4], bf[4][4];
#pragma unroll
            for (int mt = 0; mt < 4; mt++)
                ldsm4(af[mt], swadr(sA, wm + mt * 16 + arow, 2 * ks + agof));
#pragma unroll
            for (int p = 0; p < 4; p++)
                ldsm4(bf[p], swadr(sB, wn + p * 16 + brow, 2 * ks + bgof));
#pragma unroll
            for (int mt = 0; mt < 4; mt++)
#pragma unroll
                for (int p = 0; p < 4; p++) {
                    mma_tf32(acc[mt][2 * p],     af[mt], &bf[p][0]);
                    mma_tf32(acc[mt][2 * p + 1], af[mt], &bf[p][2]);
                }
        }
    }

    // ---- epilogue ----
    const int grp = lane >> 2;
    const int tig = lane & 3;
#pragma unroll
    for (int mt = 0; mt < 4; mt++) {
        const int row0 = m0 + wm + mt * 16 + grp;
#pragma unroll
        for (int nt = 0; nt < 8; nt++) {
            const int col = n0 + wn + nt * 8 + 2 * tig;
            float b0 = 0.f, b1 = 0.f;
            if (bias) { b0 = __ldg(bias + col); b1 = __ldg(bias + col + 1); }
            float2 v0, v1;
            v0.x = acc[mt][nt][0] + b0; v0.y = acc[mt][nt][1] + b1;
            v1.x = acc[mt][nt][2] + b0; v1.y = acc[mt][nt][3] + b1;
            *(float2*)(C + (long)row0 * H_SZ + col)       = v0;
            *(float2*)(C + (long)(row0 + 8) * H_SZ + col) = v1;
        }
    }
}

// -------------------- elementwise liquid step --------------------
__global__ void __launch_bounds__(256)
liquid_step_kernel(const float* __restrict__ h_in,
                   const float* __restrict__ G1,
                   const float* __restrict__ G2,
                   const float* __restrict__ C1,
                   const float* __restrict__ C2,
                   const float* __restrict__ tau_base,
                   float* __restrict__ h_out,
                   float* __restrict__ tau_out)
{
    const int idx = (blockIdx.x * 256 + threadIdx.x) * 4;
    const int j = idx & (H_SZ - 1);

    float4 g1 = *(const float4*)(G1 + idx);
    float4 g2 = *(const float4*)(G2 + idx);
    float4 c1 = *(const float4*)(C1 + idx);
    float4 c2 = *(const float4*)(C2 + idx);
    float4 hv = *(const float4*)(h_in + idx);
    float4 tb = *(const float4*)(tau_base + j);

    float4 hn, tv;
#define ONE_LANE(f)                                                        \
    {                                                                      \
        float tl  = c2.f + g1.f;                                           \
        float sg  = 1.f / (1.f + expf(-tl));                               \
        float tau = tb.f * (0.5f + sg);                                    \
        float act = tanhf(g2.f + c1.f);                                    \
        hn.f = hv.f + DT_C * (act - hv.f) / tau;                           \
        tv.f = tau;                                                        \
    }
    ONE_LANE(x) ONE_LANE(y) ONE_LANE(z) ONE_LANE(w)
#undef ONE_LANE

    *(float4*)(h_out + idx) = hn;
    if (tau_out) *(float4*)(tau_out + idx) = tv;
}

// -------------------- launcher --------------------
extern "C" void kernel_launch(void* const* d_in, const int* in_sizes, int n_in,
                              void* d_out, int out_size)
{
    (void)in_sizes; (void)n_in; (void)out_size;

    const float* x           = (const float*)d_in[0];
    const float* hidden      = (const float*)d_in[1];
    const float* W_rec       = (const float*)d_in[2];
    const float* W_in_w      = (const float*)d_in[3];
    const float* W_in_b      = (const float*)d_in[4];
    const float* tau_base    = (const float*)d_in[5];
    const float* tau_adapt_w = (const float*)d_in[6];
    const float* tau_adapt_b = (const float*)d_in[7];

    float* out_h   = (float*)d_out;
    float* out_tau = out_h + (long)B_SZ * H_SZ;

    float *C1, *C2, *G1, *G2, *hbuf;
    cudaGetSymbolAddress((void**)&C1,   g_C1);
    cudaGetSymbolAddress((void**)&C2,   g_C2);
    cudaGetSymbolAddress((void**)&G1,   g_G1);
    cudaGetSymbolAddress((void**)&G2,   g_G2);
    cudaGetSymbolAddress((void**)&hbuf, g_h);

    cudaFuncSetAttribute(gemm_dual_tf32, cudaFuncAttributeMaxDynamicSharedMemorySize, SMEM_TOTAL);

    const int ldtau = I_SZ + H_SZ;     // 3072
    dim3 gg(32, B_SZ / BM);            // 32 x 32 = 1024 CTAs, 2 per SM

    // invariant GEMMs fused: C1 = x@W_in^T + b, C2 = x@tau_x^T + tb
    gemm_dual_tf32<<<gg, THREADS, SMEM_TOTAL>>>(
        x, I_SZ,
        W_in_w, I_SZ, C1, W_in_b,
        tau_adapt_w, ldtau, C2, tau_adapt_b,
        I_SZ);

    const float* h = hidden;
    const int n_ew = (B_SZ * H_SZ) / 4 / 256;
    for (int s = 0; s < NSTEPS; s++) {
        // in-loop GEMMs fused: G1 = h@tau_h^T, G2 = h@W_rec^T
        gemm_dual_tf32<<<gg, THREADS, SMEM_TOTAL>>>(
            h, H_SZ,
            tau_adapt_w + I_SZ, ldtau, G1, nullptr,
            W_rec, H_SZ, G2, nullptr,
            H_SZ);

        float* ho = (s == NSTEPS - 1) ? out_h   : hbuf;
        float* to = (s == NSTEPS - 1) ? out_tau : nullptr;
        liquid_step_kernel<<<n_ew, 256>>>(h, G1, G2, C1, C2, tau_base, ho, to);
        h = hbuf;
    }
}

// round 9
// speedup vs baseline: 1.4466x; 1.4340x over previous
#include <cuda_runtime.h>
#include <cstdint>

// -------------------- problem constants --------------------
#define B_SZ 4096
#define I_SZ 1024
#define H_SZ 2048
#define NSTEPS 5
#define DT_C 0.1f

// -------------------- GEMM tiling (R4 layout, paired pipeline) ------------
#define BM 128
#define BN 256
#define BK 16
#define NSTAGE 6            // 3 pairs of k-tiles
#define THREADS 256

#define SA_BYTES (BM * BK * 4)                 // 8192
#define SB_BYTES (BN * BK * 4)                 // 16384
#define STAGE_BYTES (SA_BYTES + SB_BYTES)      // 24576
#define SMEM_TOTAL (NSTAGE * STAGE_BYTES)      // 147456

// -------------------- scratch --------------------
__device__ float g_C1[B_SZ * H_SZ];
__device__ float g_C2[B_SZ * H_SZ];
__device__ float g_G1[B_SZ * H_SZ];
__device__ float g_G2[B_SZ * H_SZ];
__device__ float g_h [B_SZ * H_SZ];

// -------------------- PTX helpers --------------------
__device__ __forceinline__ void cp16(uint32_t smem, const void* g) {
    asm volatile("cp.async.cg.shared.global [%0], [%1], 16;" :: "r"(smem), "l"(g) : "memory");
}
__device__ __forceinline__ void cp_commit() {
    asm volatile("cp.async.commit_group;" ::: "memory");
}
template <int N>
__device__ __forceinline__ void cp_wait() {
    asm volatile("cp.async.wait_group %0;" :: "n"(N) : "memory");
}
__device__ __forceinline__ void ldsm4(uint32_t* r, uint32_t a) {
    asm volatile("ldmatrix.sync.aligned.m8n8.x4.shared.b16 {%0,%1,%2,%3}, [%4];"
                 : "=r"(r[0]), "=r"(r[1]), "=r"(r[2]), "=r"(r[3]) : "r"(a));
}
__device__ __forceinline__ void mma_tf32(float* d, const uint32_t* a, const uint32_t* b) {
    asm volatile(
        "mma.sync.aligned.m16n8k8.row.col.f32.tf32.tf32.f32 "
        "{%0,%1,%2,%3}, {%4,%5,%6,%7}, {%8,%9}, {%0,%1,%2,%3};"
        : "+f"(d[0]), "+f"(d[1]), "+f"(d[2]), "+f"(d[3])
        : "r"(a[0]), "r"(a[1]), "r"(a[2]), "r"(a[3]), "r"(b[0]), "r"(b[1]));
}

// swizzled smem byte address for 16B chunk (row r of 64B, chunk g of 4)
__device__ __forceinline__ uint32_t swadr(uint32_t base, int r, int g) {
    const int c = g ^ (r & 3) ^ ((r >> 2) & 1);
    return base + (uint32_t)(r * 64 + c * 16);
}

// -------------------- dual-B tf32 GEMM (R4 + paired pipeline) -------------
// C_half[M, H_SZ]: tile = A[m0:+128, :K] @ Bh[n0:+256, :K]^T (+bias_h)
// grid (16, M/128): blockIdx.x selects half (B0->C0 or B1->C1) and n-block.
__global__ void __launch_bounds__(THREADS, 1)
gemm_dual_tf32(const float* __restrict__ A, int lda,
               const float* __restrict__ B0, int ldb0, float* __restrict__ C0,
               const float* __restrict__ bias0,
               const float* __restrict__ B1, int ldb1, float* __restrict__ C1,
               const float* __restrict__ bias1,
               int K)
{
    extern __shared__ __align__(1024) char smem[];
    const uint32_t sb = (uint32_t)__cvta_generic_to_shared(smem);

    const int tid  = threadIdx.x;
    const int lane = tid & 31;
    const int wid  = tid >> 5;
    const int wm   = (wid >> 2) * 64;     // warp row base: 0 / 64
    const int wn   = (wid & 3) * 64;      // warp col base: 0..192

    const int half = blockIdx.x >> 3;
    const int nblk = blockIdx.x & 7;
    const int m0 = blockIdx.y * BM;
    const int n0 = nblk * BN;

    const float* Bw   = half ? B1 : B0;
    const int    ldb  = half ? ldb1 : ldb0;
    float*       C    = half ? C1 : C0;
    const float* bias = half ? bias1 : bias0;

    // ---- loader coordinates ----
    const int lr = tid >> 2;      // 0..63
    const int lg = tid & 3;       // chunk 0..3
    const float* gA = A  + (long)(m0 + lr) * lda + lg * 4;
    const float* gB = Bw + (long)(n0 + lr) * ldb + lg * 4;
    const long strideA64 = (long)64 * lda;
    const long strideB64 = (long)64 * ldb;

    // ---- ldmatrix lane coordinates ----
    const int arow = (lane & 7) + ((lane >> 3) & 1) * 8;
    const int agof = (lane >> 4);
    const int brow = (lane & 7) + ((lane >> 4) & 1) * 8;
    const int bgof = (lane >> 3) & 1;

    float acc[4][8][4];
#pragma unroll
    for (int mt = 0; mt < 4; mt++)
#pragma unroll
        for (int nt = 0; nt < 8; nt++)
#pragma unroll
            for (int r = 0; r < 4; r++) acc[mt][nt][r] = 0.f;

    const int nK  = K / BK;
    const int nP  = nK / 2;       // pairs of k-tiles

    // ---- stage loader (6 cp.async per thread) ----
    auto load_stage = [&](int s, int kt) {
        const uint32_t sA = sb + s * STAGE_BYTES;
        const uint32_t sB = sA + SA_BYTES;
        const int koff = kt * BK;
        cp16(swadr(sA, lr,       lg), gA + koff);
        cp16(swadr(sA, lr + 64,  lg), gA + koff + strideA64);
        cp16(swadr(sB, lr,       lg), gB + koff);
        cp16(swadr(sB, lr + 64,  lg), gB + koff + strideB64);
        cp16(swadr(sB, lr + 128, lg), gB + koff + 2 * strideB64);
        cp16(swadr(sB, lr + 192, lg), gB + koff + 3 * strideB64);
    };

    // compute one stage (two k-groups)
    auto compute_stage = [&](int s) {
        const uint32_t sA = sb + s * STAGE_BYTES;
        const uint32_t sB = sA + SA_BYTES;
#pragma unroll
        for (int ks = 0; ks < 2; ks++) {
            uint32_t af[4][4], bf[4][4];
#pragma unroll
            for (int mt = 0; mt < 4; mt++)
                ldsm4(af[mt], swadr(sA, wm + mt * 16 + arow, 2 * ks + agof));
#pragma unroll
            for (int p = 0; p < 4; p++)
                ldsm4(bf[p], swadr(sB, wn + p * 16 + brow, 2 * ks + bgof));
#pragma unroll
            for (int mt = 0; mt < 4; mt++)
#pragma unroll
                for (int p = 0; p < 4; p++) {
                    mma_tf32(acc[mt][2 * p],     af[mt], &bf[p][0]);
                    mma_tf32(acc[mt][2 * p + 1], af[mt], &bf[p][2]);
                }
        }
    };

    // prologue: prefetch 2 pairs (pair j occupies stages (j%3)*2, (j%3)*2+1)
    load_stage(0, 0); load_stage(1, 1); cp_commit();
    load_stage(2, 2); load_stage(3, 3); cp_commit();

    for (int j = 0; j < nP; j++) {
        cp_wait<1>();           // pair j complete (pair j+1 may be in flight)
        __syncthreads();

        const int jl = j + 2;
        if (jl < nP) {
            const int sl = (jl % 3) * 2;
            load_stage(sl,     2 * jl);
            load_stage(sl + 1, 2 * jl + 1);
        }
        cp_commit();

        const int sc = (j % 3) * 2;
        compute_stage(sc);
        compute_stage(sc + 1);
    }

    // ---- epilogue ----
    const int grp = lane >> 2;
    const int tig = lane & 3;
#pragma unroll
    for (int mt = 0; mt < 4; mt++) {
        const int row0 = m0 + wm + mt * 16 + grp;
#pragma unroll
        for (int nt = 0; nt < 8; nt++) {
            const int col = n0 + wn + nt * 8 + 2 * tig;
            float b0 = 0.f, b1 = 0.f;
            if (bias) { b0 = __ldg(bias + col); b1 = __ldg(bias + col + 1); }
            float2 v0, v1;
            v0.x = acc[mt][nt][0] + b0; v0.y = acc[mt][nt][1] + b1;
            v1.x = acc[mt][nt][2] + b0; v1.y = acc[mt][nt][3] + b1;
            *(float2*)(C + (long)row0 * H_SZ + col)       = v0;
            *(float2*)(C + (long)(row0 + 8) * H_SZ + col) = v1;
        }
    }
}

// -------------------- elementwise liquid step --------------------
__global__ void __launch_bounds__(256)
liquid_step_kernel(const float* __restrict__ h_in,
                   const float* __restrict__ G1,
                   const float* __restrict__ G2,
                   const float* __restrict__ C1,
                   const float* __restrict__ C2,
                   const float* __restrict__ tau_base,
                   float* __restrict__ h_out,
                   float* __restrict__ tau_out)
{
    const int idx = (blockIdx.x * 256 + threadIdx.x) * 4;
    const int j = idx & (H_SZ - 1);

    float4 g1 = *(const float4*)(G1 + idx);
    float4 g2 = *(const float4*)(G2 + idx);
    float4 c1 = *(const float4*)(C1 + idx);
    float4 c2 = *(const float4*)(C2 + idx);
    float4 hv = *(const float4*)(h_in + idx);
    float4 tb = *(const float4*)(tau_base + j);

    float4 hn, tv;
#define ONE_LANE(f)                                                        \
    {                                                                      \
        float tl  = c2.f + g1.f;                                           \
        float sg  = 1.f / (1.f + expf(-tl));                               \
        float tau = tb.f * (0.5f + sg);                                    \
        float act = tanhf(g2.f + c1.f);                                    \
        hn.f = hv.f + DT_C * (act - hv.f) / tau;                           \
        tv.f = tau;                                                        \
    }
    ONE_LANE(x) ONE_LANE(y) ONE_LANE(z) ONE_LANE(w)
#undef ONE_LANE

    *(float4*)(h_out + idx) = hn;
    if (tau_out) *(float4*)(tau_out + idx) = tv;
}

// -------------------- launcher --------------------
extern "C" void kernel_launch(void* const* d_in, const int* in_sizes, int n_in,
                              void* d_out, int out_size)
{
    (void)in_sizes; (void)n_in; (void)out_size;

    const float* x           = (const float*)d_in[0];
    const float* hidden      = (const float*)d_in[1];
    const float* W_rec       = (const float*)d_in[2];
    const float* W_in_w      = (const float*)d_in[3];
    const float* W_in_b      = (const float*)d_in[4];
    const float* tau_base    = (const float*)d_in[5];
    const float* tau_adapt_w = (const float*)d_in[6];
    const float* tau_adapt_b = (const float*)d_in[7];

    float* out_h   = (float*)d_out;
    float* out_tau = out_h + (long)B_SZ * H_SZ;

    float *C1, *C2, *G1, *G2, *hbuf;
    cudaGetSymbolAddress((void**)&C1,   g_C1);
    cudaGetSymbolAddress((void**)&C2,   g_C2);
    cudaGetSymbolAddress((void**)&G1,   g_G1);
    cudaGetSymbolAddress((void**)&G2,   g_G2);
    cudaGetSymbolAddress((void**)&hbuf, g_h);

    cudaFuncSetAttribute(gemm_dual_tf32, cudaFuncAttributeMaxDynamicSharedMemorySize, SMEM_TOTAL);

    const int ldtau = I_SZ + H_SZ;     // 3072
    dim3 gg(16, B_SZ / BM);            // (16, 32) = 512 CTAs

    // invariant GEMMs fused: C1 = x@W_in^T + b, C2 = x@tau_x^T + tb
    gemm_dual_tf32<<<gg, THREADS, SMEM_TOTAL>>>(
        x, I_SZ,
        W_in_w, I_SZ, C1, W_in_b,
        tau_adapt_w, ldtau, C2, tau_adapt_b,
        I_SZ);

    const float* h = hidden;
    const int n_ew = (B_SZ * H_SZ) / 4 / 256;
    for (int s = 0; s < NSTEPS; s++) {
        // in-loop GEMMs fused: G1 = h@tau_h^T, G2 = h@W_rec^T
        gemm_dual_tf32<<<gg, THREADS, SMEM_TOTAL>>>(
            h, H_SZ,
            tau_adapt_w + I_SZ, ldtau, G1, nullptr,
            W_rec, H_SZ, G2, nullptr,
            H_SZ);

        float* ho = (s == NSTEPS - 1) ? out_h   : hbuf;
        float* to = (s == NSTEPS - 1) ? out_tau : nullptr;
        liquid_step_kernel<<<n_ew, 256>>>(h, G1, G2, C1, C2, tau_base, ho, to);
        h = hbuf;
    }
}